// round 14
// baseline (speedup 1.0000x reference)
#include <cuda_runtime.h>

#define NS 1024
#define NQ 8192
#define DD 256
#define EPS 0.05f
#define INV_EPS 20.0f
#define THRESH 1e-3f
#define MAXIT 100
#define LOG_MU -6.93146157f
#define LOG_NU -9.01083122f
#define NBLK 148
#define SKIPM 20.0f

// Scratch (allocation-free rule: __device__ globals)
__device__ float g_Ck[(size_t)NS * NQ];   // -C/eps, row-major [NS][NQ]  (32 MB)
__device__ float g_CkT[(size_t)NQ * NS];  // transpose; reused as split-K partials later
__device__ float g_us[NS];
__device__ float g_vs[NQ];
__device__ float g_r[NS];
__device__ float g_c[NQ];
__device__ float g_ls[NS];
__device__ float g_err[MAXIT];
__device__ int g_bar_count;
__device__ volatile int g_bar_sense;

// ---------------------------------------------------------------- init
__global__ void k_init() {
    int t = threadIdx.x;
    if (t == 0) { g_bar_count = 0; g_bar_sense = 0; }
    for (int i = t; i < NQ; i += 1024) g_vs[i] = 0.f;
    for (int i = t; i < NS; i += 1024) g_us[i] = 0.f;
    for (int i = t; i < MAXIT; i += 1024) g_err[i] = 0.f;
}

// ---------------------------------------------------------------- row norms
__global__ void k_norms(const float* __restrict__ X, const float* __restrict__ Y) {
    int gw = (blockIdx.x * blockDim.x + threadIdx.x) >> 5;
    int l = threadIdx.x & 31;
    if (gw >= NS + NQ) return;
    const float* p = (gw < NS) ? (X + (size_t)gw * DD) : (Y + (size_t)(gw - NS) * DD);
    const float4* p4 = (const float4*)p;
    float s = 0.f;
#pragma unroll
    for (int q = 0; q < 2; q++) {
        float4 a = p4[l + 32 * q];
        s += a.x * a.x + a.y * a.y + a.z * a.z + a.w * a.w;
    }
#pragma unroll
    for (int o = 16; o; o >>= 1) s += __shfl_xor_sync(0xffffffffu, s, o);
    if (l == 0) {
        if (gw < NS) g_r[gw] = s * INV_EPS;
        else         g_c[gw - NS] = s * INV_EPS;
    }
}

// ---------------------------------------------------------------- Ck = (2 x.y - |x|^2 - |y|^2)/eps
__global__ __launch_bounds__(256) void k_gemm_ck(const float* __restrict__ X,
                                                 const float* __restrict__ Y) {
    __shared__ float As[16][128];
    __shared__ float Bs[16][128];
    int tid = threadIdx.x;
    int tx = tid & 15, ty = tid >> 4;
    int i0 = blockIdx.y * 128, j0 = blockIdx.x * 128;
    float acc[8][8];
#pragma unroll
    for (int m = 0; m < 8; m++)
#pragma unroll
        for (int n = 0; n < 8; n++) acc[m][n] = 0.f;

    for (int k0 = 0; k0 < DD; k0 += 16) {
#pragma unroll
        for (int q = 0; q < 2; q++) {
            int lt = tid + 256 * q;
            int row = lt >> 2, kq = (lt & 3) << 2;
            float4 a = *(const float4*)(X + (size_t)(i0 + row) * DD + k0 + kq);
            As[kq + 0][row] = a.x; As[kq + 1][row] = a.y;
            As[kq + 2][row] = a.z; As[kq + 3][row] = a.w;
            float4 b = *(const float4*)(Y + (size_t)(j0 + row) * DD + k0 + kq);
            Bs[kq + 0][row] = b.x; Bs[kq + 1][row] = b.y;
            Bs[kq + 2][row] = b.z; Bs[kq + 3][row] = b.w;
        }
        __syncthreads();
#pragma unroll
        for (int k = 0; k < 16; k++) {
            float af[8], bf[8];
#pragma unroll
            for (int m = 0; m < 8; m++) af[m] = As[k][ty * 8 + m];
#pragma unroll
            for (int n = 0; n < 8; n++) bf[n] = Bs[k][tx * 8 + n];
#pragma unroll
            for (int m = 0; m < 8; m++)
#pragma unroll
                for (int n = 0; n < 8; n++) acc[m][n] += af[m] * bf[n];
        }
        __syncthreads();
    }
#pragma unroll
    for (int m = 0; m < 8; m++) {
        int i = i0 + ty * 8 + m;
        float ri = g_r[i];
#pragma unroll
        for (int n0 = 0; n0 < 8; n0 += 4) {
            int j = j0 + tx * 8 + n0;
            float4 o;
            o.x = acc[m][n0 + 0] * (2.f * INV_EPS) - ri - g_c[j + 0];
            o.y = acc[m][n0 + 1] * (2.f * INV_EPS) - ri - g_c[j + 1];
            o.z = acc[m][n0 + 2] * (2.f * INV_EPS) - ri - g_c[j + 2];
            o.w = acc[m][n0 + 3] * (2.f * INV_EPS) - ri - g_c[j + 3];
            *(float4*)(g_Ck + (size_t)i * NQ + j) = o;
        }
    }
}

// ---------------------------------------------------------------- transpose Ck -> CkT
__global__ void k_transpose() {
    __shared__ float tile[32][33];
    int bx = blockIdx.x, by = blockIdx.y;
    int txl = threadIdx.x, tyl = threadIdx.y;
    int j = bx * 32 + txl;
#pragma unroll
    for (int r = tyl; r < 32; r += 8)
        tile[r][txl] = g_Ck[(size_t)(by * 32 + r) * NQ + j];
    __syncthreads();
    int i = by * 32 + txl;
#pragma unroll
    for (int r = tyl; r < 32; r += 8)
        g_CkT[(size_t)(bx * 32 + r) * NS + i] = tile[txl][r];
}

// ---------------------------------------------------------------- lse helpers
__device__ __forceinline__ void lse_combine(float& m, float& s, float om, float os) {
    float nm = fmaxf(m, om);
    s = s * __expf(m - nm) + os * __expf(om - nm);
    m = nm;
}
__device__ __forceinline__ float warp_fmax(float v) {
#pragma unroll
    for (int o = 16; o; o >>= 1) v = fmaxf(v, __shfl_xor_sync(0xffffffffu, v, o));
    return v;
}

// scan one 512-col chunk of a row (1 warp); returns this lane's 16-elt max
__device__ __forceinline__ float row_chunk(const float4* __restrict__ c4,
                                           const float4* __restrict__ vs4,
                                           int c, int lane, float& m, float& s) {
    float vb[16];
    float cm = -1e30f;
#pragma unroll
    for (int q = 0; q < 4; q++) {
        int idx = c * 128 + lane + 32 * q;
        float4 a = __ldcg(c4 + idx);
        float4 b = vs4[idx];
        vb[4*q+0] = a.x + b.x; vb[4*q+1] = a.y + b.y;
        vb[4*q+2] = a.z + b.z; vb[4*q+3] = a.w + b.w;
    }
#pragma unroll
    for (int k = 0; k < 16; k++) cm = fmaxf(cm, vb[k]);
    float nm = fmaxf(m, cm);
    float sc = 0.f;
#pragma unroll
    for (int k = 0; k < 16; k++) sc += __expf(vb[k] - nm);
    s = s * __expf(m - nm) + sc;
    m = nm;
    return cm;
}

// pruned warp lse over one row; rowCkMax: lane<16 holds Ck chunk max for chunk==lane
__device__ __forceinline__ void row_pruned(const float4* __restrict__ c4,
                                           const float4* __restrict__ vs4,
                                           const float* __restrict__ vsm,
                                           float rowCkMax, int lane,
                                           float& m, float& s) {
    float bnd = (lane < 16) ? rowCkMax + vsm[lane] : -3e30f;
    float bmax = bnd; int cstar = lane;
#pragma unroll
    for (int o = 16; o; o >>= 1) {
        float ov = __shfl_xor_sync(0xffffffffu, bmax, o);
        int   oc = __shfl_xor_sync(0xffffffffu, cstar, o);
        if (ov > bmax || (ov == bmax && oc < cstar)) { bmax = ov; cstar = oc; }
    }
    m = -1e30f; s = 0.f;
    row_chunk(c4, vs4, cstar, lane, m, s);
    float L = warp_fmax(m);   // true max of best chunk -> lower bound of row max
#pragma unroll 1
    for (int c = 0; c < 16; c++) {
        if (c == cstar) continue;
        float bc = __shfl_sync(0xffffffffu, rowCkMax, c) + vsm[c];
        if (bc >= L - SKIPM) row_chunk(c4, vs4, c, lane, m, s);
    }
#pragma unroll
    for (int o = 16; o; o >>= 1)
        lse_combine(m, s, __shfl_xor_sync(0xffffffffu, m, o),
                    __shfl_xor_sync(0xffffffffu, s, o));
}

// scan one 128-row chunk of a column (1 warp); returns Ck-only lane max (for t==0 record)
__device__ __forceinline__ float col_chunk(const float4* __restrict__ c4,
                                           const float4* __restrict__ us4,
                                           int c, int lane, float& m, float& s) {
    int idx = c * 32 + lane;
    float4 a = __ldcg(c4 + idx);
    float4 b = us4[idx];
    float v0 = a.x + b.x, v1 = a.y + b.y, v2 = a.z + b.z, v3 = a.w + b.w;
    float cm = fmaxf(fmaxf(v0, v1), fmaxf(v2, v3));
    float nm = fmaxf(m, cm);
    float sc = __expf(v0 - nm) + __expf(v1 - nm) + __expf(v2 - nm) + __expf(v3 - nm);
    s = s * __expf(m - nm) + sc;
    m = nm;
    return fmaxf(fmaxf(a.x, a.y), fmaxf(a.z, a.w));
}

__device__ __forceinline__ void col_pruned(const float4* __restrict__ c4,
                                           const float4* __restrict__ us4,
                                           const float* __restrict__ usm,
                                           float colCkMax, int lane,
                                           float& m, float& s) {
    float bnd = (lane < 8) ? colCkMax + usm[lane] : -3e30f;
    float bmax = bnd; int cstar = lane;
#pragma unroll
    for (int o = 16; o; o >>= 1) {
        float ov = __shfl_xor_sync(0xffffffffu, bmax, o);
        int   oc = __shfl_xor_sync(0xffffffffu, cstar, o);
        if (ov > bmax || (ov == bmax && oc < cstar)) { bmax = ov; cstar = oc; }
    }
    m = -1e30f; s = 0.f;
    col_chunk(c4, us4, cstar, lane, m, s);
    float L = warp_fmax(m);
#pragma unroll 1
    for (int c = 0; c < 8; c++) {
        if (c == cstar) continue;
        float bc = __shfl_sync(0xffffffffu, colCkMax, c) + usm[c];
        if (bc >= L - SKIPM) col_chunk(c4, us4, c, lane, m, s);
    }
#pragma unroll
    for (int o = 16; o; o >>= 1)
        lse_combine(m, s, __shfl_xor_sync(0xffffffffu, m, o),
                    __shfl_xor_sync(0xffffffffu, s, o));
}

// ---------------------------------------------------------------- persistent Sinkhorn loop
// Warp-per-row (warps 0..6, row = blk + 148*w) and warp-per-column (j0 = blk*32+w, j1 = j0+4736).
// Ck chunk maxes recorded at t==0 (full scan) live in registers; bounds prune later scans.
__global__ __launch_bounds__(1024, 1) void k_sinkhorn() {
    __shared__ float4 s_vs4[NQ / 4];   // 32 KB
    __shared__ float4 s_us4[NS / 4];   // 4 KB
    __shared__ float s_vsm[16];
    __shared__ float s_usm[8];
    __shared__ float s_err;
    __shared__ int s_brk;

    const int tid = threadIdx.x;
    const int w = tid >> 5, lane = tid & 31;
    const int blk = blockIdx.x;
    const int row = blk + 148 * w;
    const bool hasRow = (w < 7) && (row < NS);
    const float4* c4row = (const float4*)(g_Ck + (size_t)(hasRow ? row : 0) * NQ);
    const int j0 = blk * 32 + w;            // always < 4736 <= NQ
    const int j1 = 4736 + j0;
    const bool hasJ1 = (j1 < NQ);
    const float4* c4c0 = (const float4*)(g_CkT + (size_t)j0 * NS);
    const float4* c4c1 = (const float4*)(g_CkT + (size_t)(hasJ1 ? j1 : 0) * NS);

    float rowCkMax = -1e30f;   // lane<16: Ck max of row chunk 'lane'
    float colCk0 = -1e30f;     // lane<8:  CkT max of col-j0 chunk 'lane'
    float colCk1 = -1e30f;
    int sense = 0;

    for (int t = 0; t < MAXIT; t++) {
        // ---- stage vs (L2 -> smem) ----
        for (int c = tid; c < NQ / 4; c += 1024)
            s_vs4[c] = __ldcg(((const float4*)g_vs) + c);
        if (tid == 0) s_err = 0.f;
        __syncthreads();
        // ---- vsm: chunk maxes of vs (16 x 512), warps 0..15 ----
        if (w < 16) {
            float vmx = -1e30f;
#pragma unroll
            for (int q = 0; q < 4; q++) {
                float4 x = s_vs4[w * 128 + lane + 32 * q];
                vmx = fmaxf(vmx, fmaxf(fmaxf(x.x, x.y), fmaxf(x.z, x.w)));
            }
            vmx = warp_fmax(vmx);
            if (lane == 0) s_vsm[w] = vmx;
        }
        __syncthreads();

        // ---- row pass ----
        if (hasRow) {
            float m = -1e30f, s = 0.f;
            if (t == 0) {
#pragma unroll 1
                for (int c = 0; c < 16; c++) {
                    float cm = row_chunk(c4row, s_vs4, c, lane, m, s);
                    float cmx = warp_fmax(cm);
                    if (lane == c) rowCkMax = cmx;   // vs==0 at t==0 -> pure Ck max
                }
#pragma unroll
                for (int o = 16; o; o >>= 1)
                    lse_combine(m, s, __shfl_xor_sync(0xffffffffu, m, o),
                                __shfl_xor_sync(0xffffffffu, s, o));
            } else {
                row_pruned(c4row, s_vs4, s_vsm, rowCkMax, lane, m, s);
            }
            if (lane == 0) {
                float un = LOG_MU - (m + __logf(s));
                float uo = g_us[row];   // own previous write (same SM)
                g_us[row] = un;
                atomicAdd(&s_err, EPS * fabsf(un - uo));
            }
        }
        __syncthreads();
        if (tid == 0) atomicAdd(&g_err[t], s_err);

        // ---- grid barrier 1 ----
        __threadfence();
        __syncthreads();
        if (tid == 0) {
            sense ^= 1;
            if (atomicAdd(&g_bar_count, 1) == NBLK - 1) {
                g_bar_count = 0;
                __threadfence();
                g_bar_sense = sense;
            } else {
                while (g_bar_sense != sense) __nanosleep(32);
                __threadfence();
            }
        }
        __syncthreads();

        // ---- stage us ----
        if (tid < NS / 4) s_us4[tid] = __ldcg(((const float4*)g_us) + tid);
        __syncthreads();
        // ---- usm: chunk maxes of us (8 x 128), warp 16 in 4-lane groups ----
        if (w == 16) {
            int cch = lane >> 2, sub = lane & 3;
            float umx = -1e30f;
#pragma unroll
            for (int q = 0; q < 8; q++) {
                float4 x = s_us4[cch * 32 + sub + 4 * q];
                umx = fmaxf(umx, fmaxf(fmaxf(x.x, x.y), fmaxf(x.z, x.w)));
            }
            umx = fmaxf(umx, __shfl_xor_sync(0xffffffffu, umx, 1));
            umx = fmaxf(umx, __shfl_xor_sync(0xffffffffu, umx, 2));
            if (sub == 0) s_usm[cch] = umx;
        }
        __syncthreads();

        // ---- col pass (rep 0) ----
        {
            float m = -1e30f, s = 0.f;
            if (t == 0) {
#pragma unroll 1
                for (int c = 0; c < 8; c++) {
                    float cko = col_chunk(c4c0, s_us4, c, lane, m, s);
                    float ckx = warp_fmax(cko);
                    if (lane == c) colCk0 = ckx;
                }
#pragma unroll
                for (int o = 16; o; o >>= 1)
                    lse_combine(m, s, __shfl_xor_sync(0xffffffffu, m, o),
                                __shfl_xor_sync(0xffffffffu, s, o));
            } else {
                col_pruned(c4c0, s_us4, s_usm, colCk0, lane, m, s);
            }
            if (lane == 0) g_vs[j0] = LOG_NU - (m + __logf(s));
        }
        // ---- col pass (rep 1) ----
        if (hasJ1) {
            float m = -1e30f, s = 0.f;
            if (t == 0) {
#pragma unroll 1
                for (int c = 0; c < 8; c++) {
                    float cko = col_chunk(c4c1, s_us4, c, lane, m, s);
                    float ckx = warp_fmax(cko);
                    if (lane == c) colCk1 = ckx;
                }
#pragma unroll
                for (int o = 16; o; o >>= 1)
                    lse_combine(m, s, __shfl_xor_sync(0xffffffffu, m, o),
                                __shfl_xor_sync(0xffffffffu, s, o));
            } else {
                col_pruned(c4c1, s_us4, s_usm, colCk1, lane, m, s);
            }
            if (lane == 0) g_vs[j1] = LOG_NU - (m + __logf(s));
        }

        // ---- grid barrier 2 ----
        __threadfence();
        __syncthreads();
        if (tid == 0) {
            sense ^= 1;
            if (atomicAdd(&g_bar_count, 1) == NBLK - 1) {
                g_bar_count = 0;
                __threadfence();
                g_bar_sense = sense;
            } else {
                while (g_bar_sense != sense) __nanosleep(32);
                __threadfence();
            }
        }
        __syncthreads();

        // ---- uniform convergence break ----
        if (tid == 0) s_brk = (__ldcg(&g_err[t]) < THRESH) ? 1 : 0;
        __syncthreads();
        if (s_brk) break;
    }

    // ---- tail: final row lse with FINAL vs -> g_ls ----
    for (int c = tid; c < NQ / 4; c += 1024)
        s_vs4[c] = __ldcg(((const float4*)g_vs) + c);
    __syncthreads();
    if (w < 16) {
        float vmx = -1e30f;
#pragma unroll
        for (int q = 0; q < 4; q++) {
            float4 x = s_vs4[w * 128 + lane + 32 * q];
            vmx = fmaxf(vmx, fmaxf(fmaxf(x.x, x.y), fmaxf(x.z, x.w)));
        }
        vmx = warp_fmax(vmx);
        if (lane == 0) s_vsm[w] = vmx;
    }
    __syncthreads();
    if (hasRow) {
        float m, s;
        row_pruned(c4row, s_vs4, s_vsm, rowCkMax, lane, m, s);
        if (lane == 0) g_ls[row] = m + __logf(s);
    }
}

// ---------------------------------------------------------------- O = exp(Ck+vs-ls) @ Y, split-K
#define SPLITK 8
#define KSLAB (NQ / SPLITK)   // 1024
__global__ __launch_bounds__(256) void k_outgemm(const float* __restrict__ Y) {
    __shared__ float As[16][68];
    __shared__ float Bs[16][256];
    __shared__ float s_vsl[KSLAB];
    __shared__ float s_ls[64];
    int tid = threadIdx.x;
    int tx = tid & 31, ty = tid >> 5;
    int ks = blockIdx.x, bm = blockIdx.y;
    int i0 = bm * 64, kbeg = ks * KSLAB;

    for (int c = tid; c < KSLAB / 4; c += 256)
        ((float4*)s_vsl)[c] = ((const float4*)(g_vs + kbeg))[c];
    if (tid < 64) s_ls[tid] = g_ls[i0 + tid];
    __syncthreads();

    float acc[8][8];
#pragma unroll
    for (int m = 0; m < 8; m++)
#pragma unroll
        for (int n = 0; n < 8; n++) acc[m][n] = 0.f;

    int ar = tid >> 2, akq = (tid & 3) << 2;
    for (int k0 = 0; k0 < KSLAB; k0 += 16) {
        {
            float4 a = __ldcg((const float4*)(g_Ck + (size_t)(i0 + ar) * NQ + kbeg + k0 + akq));
            float ls = s_ls[ar];
            As[akq + 0][ar] = __expf(a.x + s_vsl[k0 + akq + 0] - ls);
            As[akq + 1][ar] = __expf(a.y + s_vsl[k0 + akq + 1] - ls);
            As[akq + 2][ar] = __expf(a.z + s_vsl[k0 + akq + 2] - ls);
            As[akq + 3][ar] = __expf(a.w + s_vsl[k0 + akq + 3] - ls);
        }
#pragma unroll
        for (int q = 0; q < 4; q++) {
            int f4 = tid + 256 * q;
            int br = f4 >> 6, bc = (f4 & 63) << 2;
            float4 b = __ldcg((const float4*)(Y + (size_t)(kbeg + k0 + br) * DD + bc));
            *(float4*)&Bs[br][bc] = b;
        }
        __syncthreads();
#pragma unroll
        for (int k = 0; k < 16; k++) {
            float af[8], bf[8];
            *(float4*)(af + 0) = *(const float4*)&As[k][ty * 8 + 0];
            *(float4*)(af + 4) = *(const float4*)&As[k][ty * 8 + 4];
            *(float4*)(bf + 0) = *(const float4*)&Bs[k][tx * 8 + 0];
            *(float4*)(bf + 4) = *(const float4*)&Bs[k][tx * 8 + 4];
#pragma unroll
            for (int m = 0; m < 8; m++)
#pragma unroll
                for (int n = 0; n < 8; n++) acc[m][n] += af[m] * bf[n];
        }
        __syncthreads();
    }
    float* part = g_CkT + (size_t)ks * NS * DD;
#pragma unroll
    for (int m = 0; m < 8; m++) {
        float* dst = part + (size_t)(i0 + ty * 8 + m) * DD + tx * 8;
        float4 o0, o1;
        o0.x = acc[m][0]; o0.y = acc[m][1]; o0.z = acc[m][2]; o0.w = acc[m][3];
        o1.x = acc[m][4]; o1.y = acc[m][5]; o1.z = acc[m][6]; o1.w = acc[m][7];
        *(float4*)dst = o0;
        *(float4*)(dst + 4) = o1;
    }
}

// ---------------------------------------------------------------- reduce split-K + append z_query
__global__ void k_finalize(float* __restrict__ out, const float* __restrict__ Y) {
    int idx = blockIdx.x * blockDim.x + threadIdx.x;
    const float4* part = (const float4*)g_CkT;
    float4* o4 = (float4*)out;
    if (idx < NS * DD / 4) {
        float4 r = part[idx];
#pragma unroll
        for (int q = 1; q < SPLITK; q++) {
            float4 a = part[idx + q * (NS * DD / 4)];
            r.x += a.x; r.y += a.y; r.z += a.z; r.w += a.w;
        }
        o4[idx] = r;
    } else {
        o4[idx] = ((const float4*)Y)[idx - NS * DD / 4];
    }
}

// ----------------------------------------------------------------
extern "C" void kernel_launch(void* const* d_in, const int* in_sizes, int n_in,
                              void* d_out, int out_size) {
    const float* zs = (const float*)d_in[0];
    const float* zq = (const float*)d_in[1];
    if (n_in >= 2 && in_sizes[0] == NQ * DD && in_sizes[1] == NS * DD) {
        const float* t = zs; zs = zq; zq = t;
    }
    k_init<<<1, 1024>>>();
    k_norms<<<(NS + NQ) * 32 / 256, 256>>>(zs, zq);
    k_gemm_ck<<<dim3(NQ / 128, NS / 128), 256>>>(zs, zq);
    k_transpose<<<dim3(NQ / 32, NS / 32), dim3(32, 8)>>>();
    k_sinkhorn<<<NBLK, 1024>>>();
    k_outgemm<<<dim3(SPLITK, NS / 64), 256>>>(zq);
    k_finalize<<<(NS + NQ) * DD / 4 / 256, 256>>>((float*)d_out, zq);
}

// round 16
// speedup vs baseline: 1.8259x; 1.8259x over previous
#include <cuda_runtime.h>

#define NS 1024
#define NQ 8192
#define DD 256
#define EPS 0.05f
#define INV_EPS 20.0f
#define THRESH 1e-3f
#define MAXIT 100
#define LOG_MU -6.93146157f
#define LOG_NU -9.01083122f
#define NBLK 148
#define NWARP_TOT (NBLK * 32)
#define TBUILD 4
#define MARGIN 50.0f
#define DRIFT_MAX 12.0f
#define CAP 64

// Scratch (allocation-free rule: __device__ globals)
__device__ float g_Ck[(size_t)NS * NQ];   // -C/eps, row-major [NS][NQ]  (32 MB)
__device__ float g_CkT[(size_t)NQ * NS];  // transpose; reused as split-K partials later
__device__ float g_us[NS];
__device__ float g_vs[NQ];
__device__ float g_r[NS];
__device__ float g_c[NQ];
__device__ float g_ls[NS];
__device__ float g_err[MAXIT];
__device__ float g_du[MAXIT];             // per-iter max |delta us| (atomicMax, >=0)
__device__ float g_dv[MAXIT];             // per-iter max |delta vs|
__device__ int g_rowList[NS * CAP];
__device__ int g_rowCnt[NS];
__device__ int g_colList[NQ * CAP];
__device__ int g_colCnt[NQ];
__device__ int g_bar_count;
__device__ volatile int g_bar_sense;

// ---------------------------------------------------------------- init
__global__ void k_init() {
    int t = threadIdx.x;
    if (t == 0) { g_bar_count = 0; g_bar_sense = 0; }
    for (int i = t; i < NQ; i += 1024) g_vs[i] = 0.f;
    for (int i = t; i < NS; i += 1024) g_us[i] = 0.f;
    for (int i = t; i < MAXIT; i += 1024) { g_err[i] = 0.f; g_du[i] = 0.f; g_dv[i] = 0.f; }
}

// ---------------------------------------------------------------- row norms
__global__ void k_norms(const float* __restrict__ X, const float* __restrict__ Y) {
    int gw = (blockIdx.x * blockDim.x + threadIdx.x) >> 5;
    int l = threadIdx.x & 31;
    if (gw >= NS + NQ) return;
    const float* p = (gw < NS) ? (X + (size_t)gw * DD) : (Y + (size_t)(gw - NS) * DD);
    const float4* p4 = (const float4*)p;
    float s = 0.f;
#pragma unroll
    for (int q = 0; q < 2; q++) {
        float4 a = p4[l + 32 * q];
        s += a.x * a.x + a.y * a.y + a.z * a.z + a.w * a.w;
    }
#pragma unroll
    for (int o = 16; o; o >>= 1) s += __shfl_xor_sync(0xffffffffu, s, o);
    if (l == 0) {
        if (gw < NS) g_r[gw] = s * INV_EPS;
        else         g_c[gw - NS] = s * INV_EPS;
    }
}

// ---------------------------------------------------------------- Ck = (2 x.y - |x|^2 - |y|^2)/eps
__global__ __launch_bounds__(256) void k_gemm_ck(const float* __restrict__ X,
                                                 const float* __restrict__ Y) {
    __shared__ float As[16][128];
    __shared__ float Bs[16][128];
    int tid = threadIdx.x;
    int tx = tid & 15, ty = tid >> 4;
    int i0 = blockIdx.y * 128, j0 = blockIdx.x * 128;
    float acc[8][8];
#pragma unroll
    for (int m = 0; m < 8; m++)
#pragma unroll
        for (int n = 0; n < 8; n++) acc[m][n] = 0.f;

    for (int k0 = 0; k0 < DD; k0 += 16) {
#pragma unroll
        for (int q = 0; q < 2; q++) {
            int lt = tid + 256 * q;
            int row = lt >> 2, kq = (lt & 3) << 2;
            float4 a = *(const float4*)(X + (size_t)(i0 + row) * DD + k0 + kq);
            As[kq + 0][row] = a.x; As[kq + 1][row] = a.y;
            As[kq + 2][row] = a.z; As[kq + 3][row] = a.w;
            float4 b = *(const float4*)(Y + (size_t)(j0 + row) * DD + k0 + kq);
            Bs[kq + 0][row] = b.x; Bs[kq + 1][row] = b.y;
            Bs[kq + 2][row] = b.z; Bs[kq + 3][row] = b.w;
        }
        __syncthreads();
#pragma unroll
        for (int k = 0; k < 16; k++) {
            float af[8], bf[8];
#pragma unroll
            for (int m = 0; m < 8; m++) af[m] = As[k][ty * 8 + m];
#pragma unroll
            for (int n = 0; n < 8; n++) bf[n] = Bs[k][tx * 8 + n];
#pragma unroll
            for (int m = 0; m < 8; m++)
#pragma unroll
                for (int n = 0; n < 8; n++) acc[m][n] += af[m] * bf[n];
        }
        __syncthreads();
    }
#pragma unroll
    for (int m = 0; m < 8; m++) {
        int i = i0 + ty * 8 + m;
        float ri = g_r[i];
#pragma unroll
        for (int n0 = 0; n0 < 8; n0 += 4) {
            int j = j0 + tx * 8 + n0;
            float4 o;
            o.x = acc[m][n0 + 0] * (2.f * INV_EPS) - ri - g_c[j + 0];
            o.y = acc[m][n0 + 1] * (2.f * INV_EPS) - ri - g_c[j + 1];
            o.z = acc[m][n0 + 2] * (2.f * INV_EPS) - ri - g_c[j + 2];
            o.w = acc[m][n0 + 3] * (2.f * INV_EPS) - ri - g_c[j + 3];
            *(float4*)(g_Ck + (size_t)i * NQ + j) = o;
        }
    }
}

// ---------------------------------------------------------------- transpose Ck -> CkT
__global__ void k_transpose() {
    __shared__ float tile[32][33];
    int bx = blockIdx.x, by = blockIdx.y;
    int txl = threadIdx.x, tyl = threadIdx.y;
    int j = bx * 32 + txl;
#pragma unroll
    for (int r = tyl; r < 32; r += 8)
        tile[r][txl] = g_Ck[(size_t)(by * 32 + r) * NQ + j];
    __syncthreads();
    int i = by * 32 + txl;
#pragma unroll
    for (int r = tyl; r < 32; r += 8)
        g_CkT[(size_t)(bx * 32 + r) * NS + i] = tile[txl][r];
}

// ---------------------------------------------------------------- lse helpers
__device__ __forceinline__ void lse_combine(float& m, float& s, float om, float os) {
    float nm = fmaxf(m, om);
    s = s * __expf(m - nm) + os * __expf(om - nm);
    m = nm;
}
__device__ __forceinline__ void warp_lse(float& m, float& s) {
#pragma unroll
    for (int o = 16; o; o >>= 1)
        lse_combine(m, s, __shfl_xor_sync(0xffffffffu, m, o),
                    __shfl_xor_sync(0xffffffffu, s, o));
}

// Full row scan: 4 warps (128 threads) per row, R5-measured-best layout.
__device__ __forceinline__ void row_full_scan(const float4* __restrict__ c4,
                                              const float4* __restrict__ vs4,
                                              int l128, float& m, float& s) {
    m = -1e30f; s = 0.f;
#pragma unroll
    for (int c0 = 0; c0 < 16; c0 += 4) {
        float vb[16];
#pragma unroll
        for (int q = 0; q < 4; q++) {
            int idx = l128 + 128 * (c0 + q);
            float4 a = c4[idx];
            float4 b = vs4[idx];
            vb[4 * q + 0] = a.x + b.x; vb[4 * q + 1] = a.y + b.y;
            vb[4 * q + 2] = a.z + b.z; vb[4 * q + 3] = a.w + b.w;
        }
        float mc = vb[0];
#pragma unroll
        for (int k = 1; k < 16; k++) mc = fmaxf(mc, vb[k]);
        float nm = fmaxf(m, mc);
        float sc = 0.f;
#pragma unroll
        for (int k = 0; k < 16; k++) sc += __expf(vb[k] - nm);
        s = s * __expf(m - nm) + sc;
        m = nm;
    }
    warp_lse(m, s);
}

// Full col scan: 1 warp per column (R5 layout), L1-bypassed.
__device__ __forceinline__ void col_full_scan(const float4* __restrict__ c4,
                                              const float4* __restrict__ us4,
                                              int lane, float& m, float& s) {
    m = -1e30f; s = 0.f;
#pragma unroll
    for (int c0 = 0; c0 < 8; c0 += 4) {
        float vb[16];
#pragma unroll
        for (int q = 0; q < 4; q++) {
            int idx = lane + 32 * (c0 + q);
            float4 a = __ldcg(c4 + idx);
            float4 b = us4[idx];
            vb[4 * q + 0] = a.x + b.x; vb[4 * q + 1] = a.y + b.y;
            vb[4 * q + 2] = a.z + b.z; vb[4 * q + 3] = a.w + b.w;
        }
        float mc = vb[0];
#pragma unroll
        for (int k = 1; k < 16; k++) mc = fmaxf(mc, vb[k]);
        float nm = fmaxf(m, mc);
        float sc = 0.f;
#pragma unroll
        for (int k = 0; k < 16; k++) sc += __expf(vb[k] - nm);
        s = s * __expf(m - nm) + sc;
        m = nm;
    }
    warp_lse(m, s);
}

// ---------------------------------------------------------------- persistent Sinkhorn loop
// Full scans (R5 layout) for t<TBUILD; at t==TBUILD (and on drift trips) rebuild
// per-row/per-col candidate lists {elements within MARGIN of max}; gather-mode
// iterations evaluate lse over candidates only. Drift tracked via per-iter
// max|delta vs| + max|delta us|; lists valid while cumulative drift <= DRIFT_MAX.
__global__ __launch_bounds__(1024, 1) void k_sinkhorn() {
    __shared__ float4 s_vs4[NQ / 4];   // 32 KB
    __shared__ float4 s_us4[NS / 4];   // 4 KB
    __shared__ float sh_m[8][4], sh_s[8][4];
    __shared__ float sh_fm[8];
    __shared__ int s_cnt[8];
    __shared__ int s_ccnt[32];
    __shared__ float s_du[8];
    __shared__ float s_dv[32];
    __shared__ float s_err;
    __shared__ int s_brk;
    __shared__ float s_dut, s_dvt;

    const int tid = threadIdx.x;
    const int warp = tid >> 5, lane = tid & 31;
    const int rg = warp >> 2;             // row-group 0..7
    const int l128 = tid & 127;
    const int row = blockIdx.x * 8 + rg;
    const bool hasRow = (row < NS);
    const float4* c4row = (const float4*)(g_Ck + (size_t)(hasRow ? row : 0) * NQ);
    const float* s_vs = (const float*)s_vs4;
    const float* s_us = (const float*)s_us4;
    const int gw = blockIdx.x * 32 + warp;     // col id, rep0 (< 4736)
    const int j1 = gw + NWARP_TOT;
    const bool hasJ1 = (j1 < NQ);
    const float4* c4c0 = (const float4*)(g_CkT + (size_t)gw * NS);
    const float4* c4c1 = (const float4*)(g_CkT + (size_t)(hasJ1 ? j1 : 0) * NS);

    int sense = 0;
    float vprev0 = 0.f, vprev1 = 0.f;
    float Dcum = 0.f;
    bool trip = false;

    for (int t = 0; t < MAXIT; t++) {
        const bool rebuild = (t == TBUILD) || trip;
        const bool fullmode = (t < TBUILD) || rebuild;

        // ---- stage vs ----
        for (int c = tid; c < NQ / 4; c += 1024)
            s_vs4[c] = __ldcg(((const float4*)g_vs) + c);
        if (tid == 0) s_err = 0.f;
        if (tid < 8) s_du[tid] = 0.f;
        __syncthreads();

        // ---- row pass ----
        if (hasRow) {
            float m, s;
            int cnt = g_rowCnt[row];   // same-SM owner; valid only when !fullmode
            if (fullmode || cnt > CAP) {
                row_full_scan(c4row, s_vs4, l128, m, s);
            } else {
                float r = -3e30f;
                if (l128 < cnt) {
                    int j = g_rowList[(row << 6) + l128];
                    r = g_Ck[(size_t)row * NQ + j] + s_vs[j];
                }
                m = r; s = (l128 < cnt) ? 1.f : 0.f;
                warp_lse(m, s);
            }
            if (lane == 0) { sh_m[rg][warp & 3] = m; sh_s[rg][warp & 3] = s; }
        }
        __syncthreads();
        if (tid < 8) {
            int row2 = blockIdx.x * 8 + tid;
            if (row2 < NS) {
                float m = sh_m[tid][0], s = sh_s[tid][0];
#pragma unroll
                for (int q = 1; q < 4; q++) lse_combine(m, s, sh_m[tid][q], sh_s[tid][q]);
                float un = LOG_MU - (m + __logf(s));
                float uo = g_us[row2];
                g_us[row2] = un;
                float du = fabsf(un - uo);
                atomicAdd(&s_err, EPS * du);
                s_du[tid] = du;
                if (rebuild) { sh_fm[tid] = m; s_cnt[tid] = 0; }
            }
        }
        __syncthreads();
        if (rebuild) {
            if (hasRow) {
                float thr = sh_fm[rg] - MARGIN;
#pragma unroll 1
                for (int cc = 0; cc < 16; cc++) {
                    int idx = l128 + 128 * cc;
                    float4 a = c4row[idx];
                    float4 b = s_vs4[idx];
                    int jb = idx << 2;
                    if (a.x + b.x >= thr) { int p = atomicAdd(&s_cnt[rg], 1); if (p < CAP) g_rowList[(row << 6) + p] = jb; }
                    if (a.y + b.y >= thr) { int p = atomicAdd(&s_cnt[rg], 1); if (p < CAP) g_rowList[(row << 6) + p] = jb + 1; }
                    if (a.z + b.z >= thr) { int p = atomicAdd(&s_cnt[rg], 1); if (p < CAP) g_rowList[(row << 6) + p] = jb + 2; }
                    if (a.w + b.w >= thr) { int p = atomicAdd(&s_cnt[rg], 1); if (p < CAP) g_rowList[(row << 6) + p] = jb + 3; }
                }
            }
            __syncthreads();
            if (tid < 8) {
                int row2 = blockIdx.x * 8 + tid;
                if (row2 < NS) g_rowCnt[row2] = s_cnt[tid];
            }
            __syncthreads();
        }
        // publish err + row drift
        if (warp == 0) {
            float d2 = (lane < 8) ? s_du[lane] : 0.f;
#pragma unroll
            for (int o = 16; o; o >>= 1) d2 = fmaxf(d2, __shfl_xor_sync(0xffffffffu, d2, o));
            if (lane == 0) {
                atomicAdd(&g_err[t], s_err);
                atomicMax((int*)&g_du[t], __float_as_int(d2));
            }
        }

        // ---- grid barrier 1 ----
        __threadfence();
        __syncthreads();
        if (tid == 0) {
            sense ^= 1;
            if (atomicAdd(&g_bar_count, 1) == NBLK - 1) {
                g_bar_count = 0;
                __threadfence();
                g_bar_sense = sense;
            } else {
                while (g_bar_sense != sense) __nanosleep(32);
                __threadfence();
            }
        }
        __syncthreads();

        // ---- stage us ----
        if (tid < NS / 4) s_us4[tid] = __ldcg(((const float4*)g_us) + tid);
        __syncthreads();

        // ---- col pass ----
        float dvmax = 0.f;
#pragma unroll 1
        for (int rep = 0; rep < 2; rep++) {
            int j = (rep == 0) ? gw : j1;
            if (rep == 1 && !hasJ1) break;
            const float4* c4c = (rep == 0) ? c4c0 : c4c1;
            float m, s;
            int cnt = g_colCnt[j];
            bool doFull = fullmode || cnt > CAP;
            if (doFull) {
                col_full_scan(c4c, s_us4, lane, m, s);
            } else {
                const float* ckt = g_CkT + (size_t)j * NS;
                float r0 = -3e30f, r1 = -3e30f;
                if (lane < cnt) { int i = g_colList[(j << 6) + lane]; r0 = ckt[i] + s_us[i]; }
                if (lane + 32 < cnt) { int i = g_colList[(j << 6) + lane + 32]; r1 = ckt[i] + s_us[i]; }
                m = fmaxf(r0, r1);
                s = __expf(r0 - m) + __expf(r1 - m);
                warp_lse(m, s);
            }
            if (rebuild) {
                if (lane == 0) s_ccnt[warp] = 0;
                __syncwarp();
                float thr = m - MARGIN;
#pragma unroll 1
                for (int cc = 0; cc < 8; cc++) {
                    int idx = lane + 32 * cc;
                    float4 a = __ldcg(c4c + idx);
                    float4 b = s_us4[idx];
                    int ib = idx << 2;
                    if (a.x + b.x >= thr) { int p = atomicAdd(&s_ccnt[warp], 1); if (p < CAP) g_colList[(j << 6) + p] = ib; }
                    if (a.y + b.y >= thr) { int p = atomicAdd(&s_ccnt[warp], 1); if (p < CAP) g_colList[(j << 6) + p] = ib + 1; }
                    if (a.z + b.z >= thr) { int p = atomicAdd(&s_ccnt[warp], 1); if (p < CAP) g_colList[(j << 6) + p] = ib + 2; }
                    if (a.w + b.w >= thr) { int p = atomicAdd(&s_ccnt[warp], 1); if (p < CAP) g_colList[(j << 6) + p] = ib + 3; }
                }
                __syncwarp();
                if (lane == 0) g_colCnt[j] = s_ccnt[warp];
            }
            float vnew = LOG_NU - (m + __logf(s));
            if (lane == 0) g_vs[j] = vnew;
            if (rep == 0) { dvmax = fmaxf(dvmax, fabsf(vnew - vprev0)); vprev0 = vnew; }
            else          { dvmax = fmaxf(dvmax, fabsf(vnew - vprev1)); vprev1 = vnew; }
        }
        if (lane == 0) s_dv[warp] = dvmax;
        __syncthreads();
        if (warp == 0) {
            float d = s_dv[lane];
#pragma unroll
            for (int o = 16; o; o >>= 1) d = fmaxf(d, __shfl_xor_sync(0xffffffffu, d, o));
            if (lane == 0) atomicMax((int*)&g_dv[t], __float_as_int(d));
        }

        // ---- grid barrier 2 ----
        __threadfence();
        __syncthreads();
        if (tid == 0) {
            sense ^= 1;
            if (atomicAdd(&g_bar_count, 1) == NBLK - 1) {
                g_bar_count = 0;
                __threadfence();
                g_bar_sense = sense;
            } else {
                while (g_bar_sense != sense) __nanosleep(32);
                __threadfence();
            }
        }
        __syncthreads();

        // ---- convergence + drift decision (uniform) ----
        if (tid == 0) {
            s_brk = (__ldcg(&g_err[t]) < THRESH) ? 1 : 0;
            s_dut = __ldcg(&g_du[t]);
            s_dvt = __ldcg(&g_dv[t]);
        }
        __syncthreads();
        if (s_brk) break;
        if (t >= TBUILD) {
            if (rebuild) Dcum = s_dut + s_dvt;
            else         Dcum += s_dut + s_dvt;
            trip = (Dcum > DRIFT_MAX);
        }
    }

    // ---- tail: final row lse (full scan) with FINAL vs -> g_ls ----
    for (int c = tid; c < NQ / 4; c += 1024)
        s_vs4[c] = __ldcg(((const float4*)g_vs) + c);
    __syncthreads();
    if (hasRow) {
        float m, s;
        row_full_scan(c4row, s_vs4, l128, m, s);
        if (lane == 0) { sh_m[rg][warp & 3] = m; sh_s[rg][warp & 3] = s; }
    }
    __syncthreads();
    if (tid < 8) {
        int row2 = blockIdx.x * 8 + tid;
        if (row2 < NS) {
            float m = sh_m[tid][0], s = sh_s[tid][0];
#pragma unroll
            for (int q = 1; q < 4; q++) lse_combine(m, s, sh_m[tid][q], sh_s[tid][q]);
            g_ls[row2] = m + __logf(s);
        }
    }
}

// ---------------------------------------------------------------- O = exp(Ck+vs-ls) @ Y, split-K
#define SPLITK 8
#define KSLAB (NQ / SPLITK)   // 1024
__global__ __launch_bounds__(256) void k_outgemm(const float* __restrict__ Y) {
    __shared__ float As[16][68];
    __shared__ float Bs[16][256];
    __shared__ float s_vsl[KSLAB];
    __shared__ float s_ls[64];
    int tid = threadIdx.x;
    int tx = tid & 31, ty = tid >> 5;
    int ks = blockIdx.x, bm = blockIdx.y;
    int i0 = bm * 64, kbeg = ks * KSLAB;

    for (int c = tid; c < KSLAB / 4; c += 256)
        ((float4*)s_vsl)[c] = ((const float4*)(g_vs + kbeg))[c];
    if (tid < 64) s_ls[tid] = g_ls[i0 + tid];
    __syncthreads();

    float acc[8][8];
#pragma unroll
    for (int m = 0; m < 8; m++)
#pragma unroll
        for (int n = 0; n < 8; n++) acc[m][n] = 0.f;

    int ar = tid >> 2, akq = (tid & 3) << 2;
    for (int k0 = 0; k0 < KSLAB; k0 += 16) {
        {
            float4 a = __ldcg((const float4*)(g_Ck + (size_t)(i0 + ar) * NQ + kbeg + k0 + akq));
            float ls = s_ls[ar];
            As[akq + 0][ar] = __expf(a.x + s_vsl[k0 + akq + 0] - ls);
            As[akq + 1][ar] = __expf(a.y + s_vsl[k0 + akq + 1] - ls);
            As[akq + 2][ar] = __expf(a.z + s_vsl[k0 + akq + 2] - ls);
            As[akq + 3][ar] = __expf(a.w + s_vsl[k0 + akq + 3] - ls);
        }
#pragma unroll
        for (int q = 0; q < 4; q++) {
            int f4 = tid + 256 * q;
            int br = f4 >> 6, bc = (f4 & 63) << 2;
            float4 b = __ldcg((const float4*)(Y + (size_t)(kbeg + k0 + br) * DD + bc));
            *(float4*)&Bs[br][bc] = b;
        }
        __syncthreads();
#pragma unroll
        for (int k = 0; k < 16; k++) {
            float af[8], bf[8];
            *(float4*)(af + 0) = *(const float4*)&As[k][ty * 8 + 0];
            *(float4*)(af + 4) = *(const float4*)&As[k][ty * 8 + 4];
            *(float4*)(bf + 0) = *(const float4*)&Bs[k][tx * 8 + 0];
            *(float4*)(bf + 4) = *(const float4*)&Bs[k][tx * 8 + 4];
#pragma unroll
            for (int m = 0; m < 8; m++)
#pragma unroll
                for (int n = 0; n < 8; n++) acc[m][n] += af[m] * bf[n];
        }
        __syncthreads();
    }
    float* part = g_CkT + (size_t)ks * NS * DD;
#pragma unroll
    for (int m = 0; m < 8; m++) {
        float* dst = part + (size_t)(i0 + ty * 8 + m) * DD + tx * 8;
        float4 o0, o1;
        o0.x = acc[m][0]; o0.y = acc[m][1]; o0.z = acc[m][2]; o0.w = acc[m][3];
        o1.x = acc[m][4]; o1.y = acc[m][5]; o1.z = acc[m][6]; o1.w = acc[m][7];
        *(float4*)dst = o0;
        *(float4*)(dst + 4) = o1;
    }
}

// ---------------------------------------------------------------- reduce split-K + append z_query
__global__ void k_finalize(float* __restrict__ out, const float* __restrict__ Y) {
    int idx = blockIdx.x * blockDim.x + threadIdx.x;
    const float4* part = (const float4*)g_CkT;
    float4* o4 = (float4*)out;
    if (idx < NS * DD / 4) {
        float4 r = part[idx];
#pragma unroll
        for (int q = 1; q < SPLITK; q++) {
            float4 a = part[idx + q * (NS * DD / 4)];
            r.x += a.x; r.y += a.y; r.z += a.z; r.w += a.w;
        }
        o4[idx] = r;
    } else {
        o4[idx] = ((const float4*)Y)[idx - NS * DD / 4];
    }
}

// ----------------------------------------------------------------
extern "C" void kernel_launch(void* const* d_in, const int* in_sizes, int n_in,
                              void* d_out, int out_size) {
    const float* zs = (const float*)d_in[0];
    const float* zq = (const float*)d_in[1];
    if (n_in >= 2 && in_sizes[0] == NQ * DD && in_sizes[1] == NS * DD) {
        const float* t = zs; zs = zq; zq = t;
    }
    k_init<<<1, 1024>>>();
    k_norms<<<(NS + NQ) * 32 / 256, 256>>>(zs, zq);
    k_gemm_ck<<<dim3(NQ / 128, NS / 128), 256>>>(zs, zq);
    k_transpose<<<dim3(NQ / 32, NS / 32), dim3(32, 8)>>>();
    k_sinkhorn<<<NBLK, 1024>>>();
    k_outgemm<<<dim3(SPLITK, NS / 64), 256>>>(zq);
    k_finalize<<<(NS + NQ) * DD / 4 / 256, 256>>>((float*)d_out, zq);
}